// round 10
// baseline (speedup 1.0000x reference)
#include <cuda_runtime.h>
#include <cstdint>

// NoiseMixModule: out = mask*A + (1-mask)*B, mask from double-argsort ranks of u.
//
// R10 = R9 body wrapped in a PERSISTENT grid-stride loop:
//   grid = 148 SMs x 5 resident blocks = 740, each looping over 4096 tiles
//   with stride 740 (5-6 tiles/block). Eliminates 4.5 wave transitions and
//   the 47%-empty tail wave of the 4096-block launch; warps pipeline across
//   tiles (u loads of tile i+1 issue right after stores of tile i; strips
//   are warp-private so only __syncwarp is needed).
//
//   per tile (1024 rows, per-warp 128 rows / 224 float4):
//     p1: stage u to smem strip + issue group-1 A/B loads (15 LDG.128 deep)
//     p2: SWAR nibble rank counts -> mask word per row
//     p3: blend/store group 1 (k=0..3), then load/blend/store group 2 (k=4..6)

static constexpr int THREADS        = 256;
static constexpr int WARPS          = THREADS / 32;            // 8
static constexpr int ROWS_PER_WARP  = 128;
static constexpr int F4_PER_WARP    = ROWS_PER_WARP * 7 / 4;   // 224
static constexpr int ROWS_PER_BLOCK = ROWS_PER_WARP * WARPS;   // 1024
static constexpr int F4_PER_BLOCK   = F4_PER_WARP * WARPS;     // 1792
static constexpr int SMS            = 148;
static constexpr int BLOCKS_PER_SM  = 5;
static constexpr int GRID           = SMS * BLOCKS_PER_SM;     // 740

__global__ __launch_bounds__(THREADS)
void noisemix_kernel(const float4* __restrict__ A,
                     const float4* __restrict__ B,
                     const float*  __restrict__ LAM,
                     const float4* __restrict__ U,
                     float4* __restrict__ OUT,
                     int n_tiles)
{
    __shared__ float    su[ROWS_PER_BLOCK * 7];     // 28 KB, per-warp strips
    __shared__ uint32_t smask[ROWS_PER_BLOCK];      //  4 KB, SWAR mask words

    const int warp = threadIdx.x >> 5;
    const int lane = threadIdx.x & 31;

    float*    suw    = su    + warp * ROWS_PER_WARP * 7;
    uint32_t* smaskw = smask + warp * ROWS_PER_WARP;
    float4*   suw4   = reinterpret_cast<float4*>(suw);

    for (int tile = blockIdx.x; tile < n_tiles; tile += GRID) {
        const long wbase4   = (long)tile * F4_PER_BLOCK + warp * F4_PER_WARP;
        const long wrowbase = (long)tile * ROWS_PER_BLOCK + warp * ROWS_PER_WARP;

        // ---- p1a: issue u loads (coalesced float4 -> smem strip) ----
#pragma unroll
        for (int k = 0; k < 7; k++) {
            suw4[k * 32 + lane] = U[wbase4 + k * 32 + lane];
        }

        // ---- p1b: issue group-1 A/B loads (independent of u) ----
        float4 a1[4], b1[4];
#pragma unroll
        for (int k = 0; k < 4; k++) {
            const long idx4 = wbase4 + k * 32 + lane;
            a1[k] = A[idx4];
            b1[k] = B[idx4];
        }

        __syncwarp();

        // ---- p2: SWAR rank counts, 4 rows per lane ----
        // stable double-argsort rank: pair (a<b): u[a] <= u[b] -> b gains a
        // predecessor, else a does. cnt_d = nibble d of acc.
        // mask bit d = bit3 of nibble d of (acc + (8-nz)*0x01111111).
#pragma unroll
        for (int j = 0; j < 4; j++) {
            const int row = lane + j * 32;        // stride-7 LDS: conflict-free
            float uu[7];
#pragma unroll
            for (int d = 0; d < 7; d++) uu[d] = suw[row * 7 + d];

            const float lamv = LAM[wrowbase + row];
            const int   nz   = (int)floorf(7.0f * (1.0f - lamv));

            uint32_t acc = 0;
#pragma unroll
            for (int a = 0; a < 7; a++)
#pragma unroll
                for (int b = a + 1; b < 7; b++)
                    acc += (uu[a] <= uu[b]) ? (1u << (4 * b)) : (1u << (4 * a));

            smaskw[row] = acc + (uint32_t)(8 - nz) * 0x01111111u;
        }
        __syncwarp();

        // ---- p3a: blend + store group 1 (k = 0..3) ----
#pragma unroll
        for (int k = 0; k < 4; k++) {
            int le  = (k * 32 + lane) * 4;
            int row = le / 7;
            int d   = le - row * 7;

            uint32_t m = smaskw[row];
            float4 o;
            o.x = (m >> (4 * d + 3)) & 1u ? a1[k].x : b1[k].x;
            d++; if (d == 7) { d = 0; row++; m = smaskw[row]; }
            o.y = (m >> (4 * d + 3)) & 1u ? a1[k].y : b1[k].y;
            d++; if (d == 7) { d = 0; row++; m = smaskw[row]; }
            o.z = (m >> (4 * d + 3)) & 1u ? a1[k].z : b1[k].z;
            d++; if (d == 7) { d = 0; row++; m = smaskw[row]; }
            o.w = (m >> (4 * d + 3)) & 1u ? a1[k].w : b1[k].w;

            OUT[wbase4 + k * 32 + lane] = o;
        }

        // ---- p3b: load + blend + store group 2 (k = 4..6) ----
        float4 a2[3], b2[3];
#pragma unroll
        for (int k = 0; k < 3; k++) {
            const long idx4 = wbase4 + (4 + k) * 32 + lane;
            a2[k] = A[idx4];
            b2[k] = B[idx4];
        }

#pragma unroll
        for (int k = 0; k < 3; k++) {
            int le  = ((4 + k) * 32 + lane) * 4;
            int row = le / 7;
            int d   = le - row * 7;

            uint32_t m = smaskw[row];
            float4 o;
            o.x = (m >> (4 * d + 3)) & 1u ? a2[k].x : b2[k].x;
            d++; if (d == 7) { d = 0; row++; m = smaskw[row]; }
            o.y = (m >> (4 * d + 3)) & 1u ? a2[k].y : b2[k].y;
            d++; if (d == 7) { d = 0; row++; m = smaskw[row]; }
            o.z = (m >> (4 * d + 3)) & 1u ? a2[k].z : b2[k].z;
            d++; if (d == 7) { d = 0; row++; m = smaskw[row]; }
            o.w = (m >> (4 * d + 3)) & 1u ? a2[k].w : b2[k].w;

            OUT[wbase4 + (4 + k) * 32 + lane] = o;
        }

        // smem strip reuse next iteration is warp-local; loop-top writes are
        // ordered after this warp's reads by the next __syncwarp.
        __syncwarp();
    }
}

extern "C" void kernel_launch(void* const* d_in, const int* in_sizes, int n_in,
                              void* d_out, int out_size)
{
    const float4* A   = (const float4*)d_in[0];   // noise_A [B,7]
    const float4* Bp  = (const float4*)d_in[1];   // noise_B [B,7]
    const float*  LAM = (const float*)d_in[2];    // lam [B]
    const float4* U   = (const float4*)d_in[3];   // u [B,7]
    float4* OUT = (float4*)d_out;

    const int Brows   = in_sizes[2];               // 4194304
    const int n_tiles = Brows / ROWS_PER_BLOCK;    // 4096

    noisemix_kernel<<<GRID, THREADS>>>(A, Bp, LAM, U, OUT, n_tiles);
}

// round 11
// speedup vs baseline: 1.1686x; 1.1686x over previous
#include <cuda_runtime.h>
#include <cstdint>

// NoiseMixModule: out = mask*A + (1-mask)*B, mask from double-argsort ranks of u.
//
// R11 = R9 champion body, re-tiled for wave quantization:
//   512 threads (16 warps) x 128 rows/warp = 2048 rows/block, grid = 2048.
//   regs ~44 -> 2 blocks/SM (1024 thr), n_conc = 296 blocks,
//   2048/296 = 6.92 waves -> last wave 92% full (vs 53% at R4's 4096-grid).
//   Per-warp code identical to R9 (proven 83.5% DRAM schedule):
//     p1: stage u to warp-private smem strip + issue group-1 A/B loads
//     p2: SWAR nibble rank counts -> mask word per row
//     p3: blend/store k=0..3, then load/blend/store k=4..6
//   smem 64KB/block -> dynamic shared memory (attribute set host-side).

static constexpr int THREADS        = 512;
static constexpr int WARPS          = THREADS / 32;            // 16
static constexpr int ROWS_PER_WARP  = 128;
static constexpr int F4_PER_WARP    = ROWS_PER_WARP * 7 / 4;   // 224
static constexpr int ROWS_PER_BLOCK = ROWS_PER_WARP * WARPS;   // 2048
static constexpr int F4_PER_BLOCK   = F4_PER_WARP * WARPS;     // 3584

static constexpr int SMEM_U_BYTES    = ROWS_PER_BLOCK * 7 * 4;   // 57344
static constexpr int SMEM_MASK_BYTES = ROWS_PER_BLOCK * 4;       //  8192
static constexpr int SMEM_BYTES      = SMEM_U_BYTES + SMEM_MASK_BYTES; // 65536

__global__ __launch_bounds__(THREADS)
void noisemix_kernel(const float4* __restrict__ A,
                     const float4* __restrict__ B,
                     const float*  __restrict__ LAM,
                     const float4* __restrict__ U,
                     float4* __restrict__ OUT)
{
    extern __shared__ unsigned char smem_raw[];
    float*    su    = reinterpret_cast<float*>(smem_raw);
    uint32_t* smask = reinterpret_cast<uint32_t*>(smem_raw + SMEM_U_BYTES);

    const int warp = threadIdx.x >> 5;
    const int lane = threadIdx.x & 31;

    float*    suw    = su    + warp * ROWS_PER_WARP * 7;
    uint32_t* smaskw = smask + warp * ROWS_PER_WARP;
    float4*   suw4   = reinterpret_cast<float4*>(suw);

    const long wbase4   = (long)blockIdx.x * F4_PER_BLOCK + warp * F4_PER_WARP;
    const long wrowbase = (long)blockIdx.x * ROWS_PER_BLOCK + warp * ROWS_PER_WARP;

    // ---- p1a: issue u loads (coalesced float4 -> smem strip) ----
#pragma unroll
    for (int k = 0; k < 7; k++) {
        suw4[k * 32 + lane] = U[wbase4 + k * 32 + lane];
    }

    // ---- p1b: issue group-1 A/B loads (independent of u) ----
    float4 a1[4], b1[4];
#pragma unroll
    for (int k = 0; k < 4; k++) {
        const long idx4 = wbase4 + k * 32 + lane;
        a1[k] = A[idx4];
        b1[k] = B[idx4];
    }

    __syncwarp();

    // ---- p2: SWAR rank counts, 4 rows per lane ----
    // stable double-argsort rank: pair (a<b): u[a] <= u[b] -> b gains a
    // predecessor, else a does. cnt_d lives in nibble d of acc.
    // mask bit d = bit3 of nibble d of (acc + (8-nz)*0x01111111).
#pragma unroll
    for (int j = 0; j < 4; j++) {
        const int row = lane + j * 32;           // stride-7 LDS: conflict-free
        float uu[7];
#pragma unroll
        for (int d = 0; d < 7; d++) uu[d] = suw[row * 7 + d];

        const float lamv = LAM[wrowbase + row];  // coalesced 4B/lane
        const int   nz   = (int)floorf(7.0f * (1.0f - lamv));

        uint32_t acc = 0;
#pragma unroll
        for (int a = 0; a < 7; a++)
#pragma unroll
            for (int b = a + 1; b < 7; b++)
                acc += (uu[a] <= uu[b]) ? (1u << (4 * b)) : (1u << (4 * a));

        smaskw[row] = acc + (uint32_t)(8 - nz) * 0x01111111u;
    }
    __syncwarp();

    // ---- p3a: blend + store group 1 (k = 0..3) ----
#pragma unroll
    for (int k = 0; k < 4; k++) {
        int le  = (k * 32 + lane) * 4;          // element idx within warp tile
        int row = le / 7;
        int d   = le - row * 7;

        uint32_t m = smaskw[row];
        float4 o;
        o.x = (m >> (4 * d + 3)) & 1u ? a1[k].x : b1[k].x;
        d++; if (d == 7) { d = 0; row++; m = smaskw[row]; }
        o.y = (m >> (4 * d + 3)) & 1u ? a1[k].y : b1[k].y;
        d++; if (d == 7) { d = 0; row++; m = smaskw[row]; }
        o.z = (m >> (4 * d + 3)) & 1u ? a1[k].z : b1[k].z;
        d++; if (d == 7) { d = 0; row++; m = smaskw[row]; }
        o.w = (m >> (4 * d + 3)) & 1u ? a1[k].w : b1[k].w;

        OUT[wbase4 + k * 32 + lane] = o;
    }

    // ---- p3b: load + blend + store group 2 (k = 4..6) ----
    float4 a2[3], b2[3];
#pragma unroll
    for (int k = 0; k < 3; k++) {
        const long idx4 = wbase4 + (4 + k) * 32 + lane;
        a2[k] = A[idx4];
        b2[k] = B[idx4];
    }

#pragma unroll
    for (int k = 0; k < 3; k++) {
        int le  = ((4 + k) * 32 + lane) * 4;
        int row = le / 7;
        int d   = le - row * 7;

        uint32_t m = smaskw[row];
        float4 o;
        o.x = (m >> (4 * d + 3)) & 1u ? a2[k].x : b2[k].x;
        d++; if (d == 7) { d = 0; row++; m = smaskw[row]; }
        o.y = (m >> (4 * d + 3)) & 1u ? a2[k].y : b2[k].y;
        d++; if (d == 7) { d = 0; row++; m = smaskw[row]; }
        o.z = (m >> (4 * d + 3)) & 1u ? a2[k].z : b2[k].z;
        d++; if (d == 7) { d = 0; row++; m = smaskw[row]; }
        o.w = (m >> (4 * d + 3)) & 1u ? a2[k].w : b2[k].w;

        OUT[wbase4 + (4 + k) * 32 + lane] = o;
    }
}

extern "C" void kernel_launch(void* const* d_in, const int* in_sizes, int n_in,
                              void* d_out, int out_size)
{
    const float4* A   = (const float4*)d_in[0];   // noise_A [B,7]
    const float4* Bp  = (const float4*)d_in[1];   // noise_B [B,7]
    const float*  LAM = (const float*)d_in[2];    // lam [B]
    const float4* U   = (const float4*)d_in[3];   // u [B,7]
    float4* OUT = (float4*)d_out;

    // one-time opt-in for >48KB dynamic smem (host-side attribute, no alloc)
    static bool attr_done = false;
    if (!attr_done) {
        cudaFuncSetAttribute(noisemix_kernel,
                             cudaFuncAttributeMaxDynamicSharedMemorySize,
                             SMEM_BYTES);
        attr_done = true;
    }

    const int Brows  = in_sizes[2];                // 4194304
    const int blocks = Brows / ROWS_PER_BLOCK;     // 2048

    noisemix_kernel<<<blocks, THREADS, SMEM_BYTES>>>(A, Bp, LAM, U, OUT);
}